// round 16
// baseline (speedup 1.0000x reference)
#include <cuda_runtime.h>
#include <cuda_fp16.h>

#define SB   32      // S*B
#define NTOK 2048    // N
#define KK   16      // K
#define DD   32      // D
#define HH   128     // H

#define TPB   256    // threads per block (8 warps)
#define TOKPB 128    // tokens per block (single-wave grid: 512 blocks)
#define NW    8      // warps (warp = 16-h slice)

#define XLD   40     // x_s row stride (halfs): 80B = 5 granules (odd)
#define WLD   136    // W_s row stride (halfs): 272B = 17 granules (odd)
#define HXLD  68     // hx row stride (u32): 272B; bank stride 4 -> phase-distinct
#define PRT   17     // part_s row stride (u32): odd -> conflict-free STS

// smem overlays (bytes). Stage 1: x | W | hx. Stage 2: hkb | part.
#define X_OFF    0                          // 128*40*2  = 10240
#define W_OFF    10240                      // 32*136*2  =  8704 (end 18944)
#define HX_OFF   18944                      // 128*68*4  = 34816 (end 53760)
#define HKB_OFF  0                          // 1024*4    =  4096 (over dead x)
#define PART_OFF 4096                       // 8*64*17*4 = 34816 (end 38912; over dead W/hx)
#define SMEM_TOTAL 53760

// hk[k,h]+b1[h] per (s,b), packed half2. 32*16*64 u32 = 128 KB.
__device__ unsigned g_hkbh[SB * KK * (HH / 2)];

__device__ __forceinline__ __half2 tanh2(__half2 v) {
    unsigned vi = *reinterpret_cast<unsigned*>(&v), yi;
    asm("tanh.approx.f16x2 %0, %1;" : "=r"(yi) : "r"(vi));
    return *reinterpret_cast<__half2*>(&yi);
}
__device__ __forceinline__ __half2 asH2(unsigned u) { return *reinterpret_cast<__half2*>(&u); }
__device__ __forceinline__ unsigned h2bits(__half2 h) { return *reinterpret_cast<unsigned*>(&h); }
__device__ __forceinline__ unsigned smem_u32(const void* p) {
    return (unsigned)__cvta_generic_to_shared(p);
}

// ---------------------------------------------------------------------------
// Prep: hkbh[sb,k,h/2] = half2( sum_d mu*Wm + tau*Wt + b1 )
// ---------------------------------------------------------------------------
__global__ __launch_bounds__(TPB)
void prep_kernel(const float* __restrict__ mu,
                 const float* __restrict__ tau,
                 const float* __restrict__ W1,
                 const float* __restrict__ b1) {
    int sb = blockIdx.y;
    int k  = blockIdx.x * 4 + (threadIdx.x >> 6);
    int hp = threadIdx.x & 63;
    const float* mur  = mu  + (sb * KK + k) * DD;
    const float* taur = tau + (sb * KK + k) * DD;
    float2 b = *reinterpret_cast<const float2*>(b1 + 2 * hp);
    float s0 = b.x, s1 = b.y;
    #pragma unroll
    for (int d = 0; d < DD; d++) {
        float m = mur[d], ta = taur[d];
        float2 wm = __ldg(reinterpret_cast<const float2*>(W1 + (DD     + d) * HH + 2 * hp));
        float2 wt = __ldg(reinterpret_cast<const float2*>(W1 + (2 * DD + d) * HH + 2 * hp));
        s0 = fmaf(m, wm.x, s0);  s1 = fmaf(m, wm.y, s1);
        s0 = fmaf(ta, wt.x, s0); s1 = fmaf(ta, wt.y, s1);
    }
    g_hkbh[(sb * KK + k) * (HH / 2) + hp] = h2bits(__floats2half2_rn(s0, s1));
}

// ---------------------------------------------------------------------------
// Main (single wave): 512 blocks, 8 warps x 128 tokens each.
// Phase A: f16-acc mma.m16n8k16 (8 m-tiles), per-mt epilogue -> hx overlay.
// Phase B: two t-rounds; each computes 2 token-groups x 16 k (all-f16 loop,
// unroll 4) then reduces + softmaxes its 64 tokens in-round.
// ---------------------------------------------------------------------------
__global__ __launch_bounds__(TPB, 4)
void main_kernel(const float* __restrict__ x,
                 const float* __restrict__ W1,
                 const float* __restrict__ W2,
                 float* __restrict__ out) {
    extern __shared__ __align__(16) unsigned char smraw[];
    __half*   x_s    = reinterpret_cast<__half*>(smraw + X_OFF);
    __half*   W_s    = reinterpret_cast<__half*>(smraw + W_OFF);
    unsigned* hx_s   = reinterpret_cast<unsigned*>(smraw + HX_OFF);
    unsigned* hkb_s  = reinterpret_cast<unsigned*>(smraw + HKB_OFF);
    unsigned* part_s = reinterpret_cast<unsigned*>(smraw + PART_OFF);

    const int tid  = threadIdx.x;
    const int w    = tid >> 5;
    const int lane = tid & 31;
    const int sb   = blockIdx.y;
    const int tokb = blockIdx.x * TOKPB;
    const int h0   = w * 16;

    // Stage x as f16 (128 tok x 8 quads = 1024 float4)
    #pragma unroll
    for (int it = 0; it < 4; it++) {
        int idx = tid + it * TPB;
        int tok = idx >> 3, q = idx & 7;
        float4 v = *reinterpret_cast<const float4*>(
            x + ((size_t)sb * NTOK + tokb + tok) * DD + q * 4);
        unsigned* p = reinterpret_cast<unsigned*>(x_s + tok * XLD + q * 4);
        p[0] = h2bits(__floats2half2_rn(v.x, v.y));
        p[1] = h2bits(__floats2half2_rn(v.z, v.w));
    }
    // Stage Wx (rows 0..31 of W1) as f16
    #pragma unroll
    for (int it = 0; it < 8; it++) {
        int idx = tid + it * TPB;                    // 2048 half2
        int k = idx >> 6, n2 = idx & 63;
        float2 wv = __ldg(reinterpret_cast<const float2*>(W1 + k * HH + n2 * 2));
        reinterpret_cast<unsigned*>(W_s + k * WLD)[n2] = h2bits(__floats2half2_rn(wv.x, wv.y));
    }
    __syncthreads();

    // ---- Phase A: mma f16 acc, 8 m-tiles, per-mt epilogue ----
    {
        const unsigned xb = smem_u32(x_s);
        const unsigned wb = smem_u32(W_s);
        const int g = lane >> 2, j = lane & 3;

        unsigned bf[2][2][2];                         // [kh][nt][reg]
        #pragma unroll
        for (int kh = 0; kh < 2; kh++)
            #pragma unroll
            for (int nt = 0; nt < 2; nt++) {
                unsigned addrB = wb + ((kh * 16 + (lane & 15)) * WLD + h0 + nt * 8) * 2;
                asm volatile("ldmatrix.sync.aligned.m8n8.x2.trans.shared.b16 {%0,%1}, [%2];"
                             : "=r"(bf[kh][nt][0]), "=r"(bf[kh][nt][1]) : "r"(addrB));
            }

        #pragma unroll
        for (int mt = 0; mt < 8; mt++) {
            unsigned d0[2] = {0u, 0u}, d1[2] = {0u, 0u};
            #pragma unroll
            for (int kh = 0; kh < 2; kh++) {
                int mA = mt * 16 + (lane & 7) + ((lane & 8) ? 8 : 0);
                int kA = kh * 16 + ((lane & 16) ? 8 : 0);
                unsigned addrA = xb + (mA * XLD + kA) * 2;
                unsigned a0, a1, a2, a3;
                asm volatile("ldmatrix.sync.aligned.m8n8.x4.shared.b16 {%0,%1,%2,%3}, [%4];"
                             : "=r"(a0), "=r"(a1), "=r"(a2), "=r"(a3) : "r"(addrA));
                #pragma unroll
                for (int nt = 0; nt < 2; nt++) {
                    asm volatile(
                        "mma.sync.aligned.m16n8k16.row.col.f16.f16.f16.f16 "
                        "{%0,%1}, {%2,%3,%4,%5}, {%6,%7}, {%0,%1};"
                        : "+r"(d0[nt]), "+r"(d1[nt])
                        : "r"(a0), "r"(a1), "r"(a2), "r"(a3),
                          "r"(bf[kh][nt][0]), "r"(bf[kh][nt][1]));
                }
            }
            #pragma unroll
            for (int nt = 0; nt < 2; nt++) {
                int col = h0 / 2 + nt * 4 + j;        // global h-pair index
                hx_s[(mt * 16 + g)     * HXLD + col] = d0[nt];
                hx_s[(mt * 16 + g + 8) * HXLD + col] = d1[nt];
            }
        }
    }
    __syncthreads();

    // Pull hx for all 4 token groups (warp's h-slice) into registers
    unsigned hxh[4][8];
    #pragma unroll
    for (int t = 0; t < 4; t++) {
        const uint4* hp = reinterpret_cast<const uint4*>(&hx_s[(t * 32 + lane) * HXLD + w * 8]);
        uint4 A = hp[0], B = hp[1];
        hxh[t][0] = A.x; hxh[t][1] = A.y; hxh[t][2] = A.z; hxh[t][3] = A.w;
        hxh[t][4] = B.x; hxh[t][5] = B.y; hxh[t][6] = B.z; hxh[t][7] = B.w;
    }
    // Stage hkb into the dead x region
    for (int i = tid; i < KK * (HH / 2); i += TPB)
        hkb_s[i] = g_hkbh[sb * KK * (HH / 2) + i];
    // W2 slice as half2
    __half2 w2h[8];
    {
        const float4* w2p = reinterpret_cast<const float4*>(W2 + h0);
        #pragma unroll
        for (int q = 0; q < 4; q++) {
            float4 wv = __ldg(w2p + q);
            w2h[2 * q + 0] = __floats2half2_rn(wv.x, wv.y);
            w2h[2 * q + 1] = __floats2half2_rn(wv.z, wv.w);
        }
    }
    __syncthreads();

    // ---- Phase B: two t-rounds, each followed by in-round reduce+softmax ----
    #pragma unroll
    for (int r = 0; r < 2; r++) {
        #pragma unroll 4
        for (int k = 0; k < KK; k++) {
            const uint4* hkp = reinterpret_cast<const uint4*>(&hkb_s[k * (HH / 2) + w * 8]);
            uint4 hA = hkp[0], hB = hkp[1];          // warp-uniform LDS.128
            #pragma unroll
            for (int tt = 0; tt < 2; tt++) {
                const int t = r * 2 + tt;
                __half2 a0, a1, a2, a3;
                a0 = __hmul2(tanh2(__hadd2(asH2(hxh[t][0]), asH2(hA.x))), w2h[0]);
                a1 = __hmul2(tanh2(__hadd2(asH2(hxh[t][1]), asH2(hA.y))), w2h[1]);
                a2 = __hmul2(tanh2(__hadd2(asH2(hxh[t][2]), asH2(hA.z))), w2h[2]);
                a3 = __hmul2(tanh2(__hadd2(asH2(hxh[t][3]), asH2(hA.w))), w2h[3]);
                a0 = __hfma2(tanh2(__hadd2(asH2(hxh[t][4]), asH2(hB.x))), w2h[4], a0);
                a1 = __hfma2(tanh2(__hadd2(asH2(hxh[t][5]), asH2(hB.y))), w2h[5], a1);
                a2 = __hfma2(tanh2(__hadd2(asH2(hxh[t][6]), asH2(hB.z))), w2h[6], a2);
                a3 = __hfma2(tanh2(__hadd2(asH2(hxh[t][7]), asH2(hB.w))), w2h[7], a3);
                __half2 a = __hadd2(__hadd2(a0, a1), __hadd2(a2, a3));
                part_s[(w * 64 + tt * 32 + lane) * PRT + k] = h2bits(a);
            }
        }
        __syncthreads();

        // Reduce (f32) + softmax for tokens r*64 .. r*64+63
        {
            const int tokr = tid >> 2;               // 0..63
            const int kq   = tid & 3;
            float gg[4];
            #pragma unroll
            for (int j = 0; j < 4; j++) {
                int k = 4 * kq + j;
                float s = 0.f;
                #pragma unroll
                for (int ww = 0; ww < NW; ww++) {
                    float2 f = __half22float2(asH2(part_s[(ww * 64 + tokr) * PRT + k]));
                    s += f.x + f.y;
                }
                gg[j] = s;
            }
            float m = fmaxf(fmaxf(gg[0], gg[1]), fmaxf(gg[2], gg[3]));
            m = fmaxf(m, __shfl_xor_sync(0xffffffffu, m, 1));
            m = fmaxf(m, __shfl_xor_sync(0xffffffffu, m, 2));
            float e0 = __expf(gg[0] - m), e1 = __expf(gg[1] - m);
            float e2 = __expf(gg[2] - m), e3 = __expf(gg[3] - m);
            float s = (e0 + e1) + (e2 + e3);
            s += __shfl_xor_sync(0xffffffffu, s, 1);
            s += __shfl_xor_sync(0xffffffffu, s, 2);
            float inv = __fdividef(1.f, s);
            float4 o;
            o.x = e0 * inv; o.y = e1 * inv; o.z = e2 * inv; o.w = e3 * inv;
            reinterpret_cast<float4*>(
                out + ((size_t)sb * NTOK + tokb + r * 64 + tokr) * KK)[kq] = o;
        }
        __syncthreads();
    }
}

extern "C" void kernel_launch(void* const* d_in, const int* in_sizes, int n_in,
                              void* d_out, int out_size) {
    const float* x   = (const float*)d_in[0];
    const float* mu  = (const float*)d_in[1];
    const float* tau = (const float*)d_in[2];
    const float* W1  = (const float*)d_in[3];
    const float* b1  = (const float*)d_in[4];
    const float* W2  = (const float*)d_in[5];
    // d_in[6] = b2: cancels in softmax, unused.
    float* out = (float*)d_out;

    cudaFuncSetAttribute(main_kernel,
                         cudaFuncAttributeMaxDynamicSharedMemorySize, SMEM_TOTAL);
    prep_kernel<<<dim3(KK / 4, SB), TPB>>>(mu, tau, W1, b1);
    main_kernel<<<dim3(NTOK / TOKPB, SB), TPB, SMEM_TOTAL>>>(x, W1, W2, out);
}

// round 17
// speedup vs baseline: 1.0934x; 1.0934x over previous
#include <cuda_runtime.h>
#include <cuda_fp16.h>

#define SB   32      // S*B
#define NTOK 2048    // N
#define KK   16      // K
#define DD   32      // D
#define HH   128     // H

#define TPB   256    // threads per block (8 warps)
#define TOKPB 64     // tokens per block
#define NW    8      // warps (warp = 16-h slice)
#define TT    2      // token-groups per thread

#define XLD   40     // x_s row stride (halfs)
#define WLD   136    // W_s row stride (halfs)
#define HXP   11     // hx16 row stride (u32)
#define PRT   17     // part_s row stride (u32)

// smem overlay offsets (bytes)
#define HKB_OFF  0                         // 4096 B
#define X_OFF    4096                      // 5120 B
#define W_OFF    (X_OFF + 5120)            // 8704 B (end 17920)
#define HX_OFF   17920                     // 22528 B (end 40448)
#define PART_OFF 4096                      // 34816 B (end 38912)
#define SMEM_TOTAL 40448

typedef unsigned long long u64;

// hk[k,h]+b1[h] per (s,b), packed half2. 128 KB.
__device__ unsigned g_hkbh[SB * KK * (HH / 2)];

__device__ __forceinline__ u64 pk2(float lo, float hi) {
    u64 r; asm("mov.b64 %0, {%1, %2};" : "=l"(r) : "f"(lo), "f"(hi)); return r;
}
__device__ __forceinline__ void upk2(float& lo, float& hi, u64 v) {
    asm("mov.b64 {%0, %1}, %2;" : "=f"(lo), "=f"(hi) : "l"(v));
}
__device__ __forceinline__ u64 fma2(u64 a, u64 b, u64 c) {
    u64 r; asm("fma.rn.f32x2 %0, %1, %2, %3;" : "=l"(r) : "l"(a), "l"(b), "l"(c)); return r;
}
__device__ __forceinline__ u64 mul2(u64 a, u64 b) {
    u64 r; asm("mul.rn.f32x2 %0, %1, %2;" : "=l"(r) : "l"(a), "l"(b)); return r;
}
__device__ __forceinline__ __half2 tanh2(__half2 v) {
    unsigned vi = *reinterpret_cast<unsigned*>(&v), yi;
    asm("tanh.approx.f16x2 %0, %1;" : "=r"(yi) : "r"(vi));
    return *reinterpret_cast<__half2*>(&yi);
}
__device__ __forceinline__ __half2 asH2(unsigned u) { return *reinterpret_cast<__half2*>(&u); }
__device__ __forceinline__ unsigned h2bits(__half2 h) { return *reinterpret_cast<unsigned*>(&h); }
__device__ __forceinline__ unsigned smem_u32(const void* p) {
    return (unsigned)__cvta_generic_to_shared(p);
}

// FMA-pipe tanh: Pade[5/4] in packed f32x2, clamp +-3.2, magic rcp + 2 NR.
struct PadeC { u64 c1, c2, c3, c4, one; };

__device__ __forceinline__ __half2 tanh_pade(__half2 s, const PadeC& C) {
    s = __hmin2(s, __floats2half2_rn(3.2f, 3.2f));
    s = __hmax2(s, __floats2half2_rn(-3.2f, -3.2f));
    float2 f = __half22float2(s);
    u64 x  = pk2(f.x, f.y);
    u64 u2 = mul2(x, x);
    u64 n  = fma2(fma2(u2, C.c2, C.c1), u2, C.one);   // 1 + u/9 + u^2/945
    u64 d  = fma2(fma2(u2, C.c4, C.c3), u2, C.one);   // 1 + 4u/9 + u^2/63
    unsigned dl, dh;
    asm("mov.b64 {%0,%1}, %2;" : "=r"(dl), "=r"(dh) : "l"(d));
    dl = 0x7EF311C3u - dl;
    dh = 0x7EF311C3u - dh;
    u64 r;
    asm("mov.b64 %0, {%1,%2};" : "=l"(r) : "r"(dl), "r"(dh));
    u64 nd = d ^ 0x8000000080000000ull;               // -d
    u64 t  = fma2(nd, r, C.one); r = fma2(r, t, r);   // NR step 1
    t      = fma2(nd, r, C.one); r = fma2(r, t, r);   // NR step 2
    u64 res = mul2(mul2(x, n), r);
    float lo, hi;
    upk2(lo, hi, res);
    return __floats2half2_rn(lo, hi);
}

// ---------------------------------------------------------------------------
// Prep: hkbh[sb,k,h/2] = half2( sum_d mu*Wm + tau*Wt + b1 )
// ---------------------------------------------------------------------------
__global__ __launch_bounds__(TPB)
void prep_kernel(const float* __restrict__ mu,
                 const float* __restrict__ tau,
                 const float* __restrict__ W1,
                 const float* __restrict__ b1) {
    int sb = blockIdx.y;
    int k  = blockIdx.x * 4 + (threadIdx.x >> 6);
    int hp = threadIdx.x & 63;
    const float* mur  = mu  + (sb * KK + k) * DD;
    const float* taur = tau + (sb * KK + k) * DD;
    float2 b = *reinterpret_cast<const float2*>(b1 + 2 * hp);
    float s0 = b.x, s1 = b.y;
    #pragma unroll
    for (int d = 0; d < DD; d++) {
        float m = mur[d], ta = taur[d];
        float2 wm = __ldg(reinterpret_cast<const float2*>(W1 + (DD     + d) * HH + 2 * hp));
        float2 wt = __ldg(reinterpret_cast<const float2*>(W1 + (2 * DD + d) * HH + 2 * hp));
        s0 = fmaf(m, wm.x, s0);  s1 = fmaf(m, wm.y, s1);
        s0 = fmaf(ta, wt.x, s0); s1 = fmaf(ta, wt.y, s1);
    }
    g_hkbh[(sb * KK + k) * (HH / 2) + hp] = h2bits(__floats2half2_rn(s0, s1));
}

// ---------------------------------------------------------------------------
// Main (R15 structure): tensor-core phase A (f16 acc), pipe-balanced phase B:
// slots q=0,2,3,4,6,7 via MUFU tanh2; slots q=1,5 via FMA-pipe Pade.
// ---------------------------------------------------------------------------
__global__ __launch_bounds__(TPB, 3)
void main_kernel(const float* __restrict__ x,
                 const float* __restrict__ W1,
                 const float* __restrict__ W2,
                 float* __restrict__ out) {
    __shared__ __align__(16) unsigned char smraw[SMEM_TOTAL];
    unsigned* hkb_s  = reinterpret_cast<unsigned*>(smraw + HKB_OFF);
    __half*   x_s    = reinterpret_cast<__half*>(smraw + X_OFF);
    __half*   W_s    = reinterpret_cast<__half*>(smraw + W_OFF);
    unsigned* hx_s   = reinterpret_cast<unsigned*>(smraw + HX_OFF);
    unsigned* part_s = reinterpret_cast<unsigned*>(smraw + PART_OFF);

    const int tid  = threadIdx.x;
    const int w    = tid >> 5;
    const int lane = tid & 31;
    const int sb   = blockIdx.y;
    const int tokb = blockIdx.x * TOKPB;
    const int h0   = w * 16;

    for (int i = tid; i < KK * (HH / 2); i += TPB)
        hkb_s[i] = g_hkbh[sb * KK * (HH / 2) + i];

    // Stage x as f16
    #pragma unroll
    for (int it = 0; it < 2; it++) {
        int idx = tid + it * TPB;
        int tok = idx >> 3, q = idx & 7;
        float4 v = *reinterpret_cast<const float4*>(
            x + ((size_t)sb * NTOK + tokb + tok) * DD + q * 4);
        unsigned* p = reinterpret_cast<unsigned*>(x_s + tok * XLD + q * 4);
        p[0] = h2bits(__floats2half2_rn(v.x, v.y));
        p[1] = h2bits(__floats2half2_rn(v.z, v.w));
    }
    // Stage Wx as f16
    #pragma unroll
    for (int it = 0; it < 8; it++) {
        int idx = tid + it * TPB;
        int k = idx >> 6, n2 = idx & 63;
        float2 wv = __ldg(reinterpret_cast<const float2*>(W1 + k * HH + n2 * 2));
        reinterpret_cast<unsigned*>(W_s + k * WLD)[n2] = h2bits(__floats2half2_rn(wv.x, wv.y));
    }
    __syncthreads();

    // ---- Phase A: mma.m16n8k16 f16 acc; per-mt epilogue ----
    {
        const unsigned xb = smem_u32(x_s);
        const unsigned wb = smem_u32(W_s);
        const int g = lane >> 2, j = lane & 3;

        unsigned bf[2][2][2];
        #pragma unroll
        for (int kh = 0; kh < 2; kh++)
            #pragma unroll
            for (int nt = 0; nt < 2; nt++) {
                unsigned addrB = wb + ((kh * 16 + (lane & 15)) * WLD + h0 + nt * 8) * 2;
                asm volatile("ldmatrix.sync.aligned.m8n8.x2.trans.shared.b16 {%0,%1}, [%2];"
                             : "=r"(bf[kh][nt][0]), "=r"(bf[kh][nt][1]) : "r"(addrB));
            }

        #pragma unroll
        for (int mt = 0; mt < 4; mt++) {
            unsigned d0[2] = {0u, 0u}, d1[2] = {0u, 0u};
            #pragma unroll
            for (int kh = 0; kh < 2; kh++) {
                int mA = mt * 16 + (lane & 7) + ((lane & 8) ? 8 : 0);
                int kA = kh * 16 + ((lane & 16) ? 8 : 0);
                unsigned addrA = xb + (mA * XLD + kA) * 2;
                unsigned a0, a1, a2, a3;
                asm volatile("ldmatrix.sync.aligned.m8n8.x4.shared.b16 {%0,%1,%2,%3}, [%4];"
                             : "=r"(a0), "=r"(a1), "=r"(a2), "=r"(a3) : "r"(addrA));
                #pragma unroll
                for (int nt = 0; nt < 2; nt++) {
                    asm volatile(
                        "mma.sync.aligned.m16n8k16.row.col.f16.f16.f16.f16 "
                        "{%0,%1}, {%2,%3,%4,%5}, {%6,%7}, {%0,%1};"
                        : "+r"(d0[nt]), "+r"(d1[nt])
                        : "r"(a0), "r"(a1), "r"(a2), "r"(a3),
                          "r"(bf[kh][nt][0]), "r"(bf[kh][nt][1]));
                }
            }
            #pragma unroll
            for (int nt = 0; nt < 2; nt++) {
                int col = nt * 4 + j;
                hx_s[(w * 64 + mt * 16 + g)     * HXP + col] = d0[nt];
                hx_s[(w * 64 + mt * 16 + g + 8) * HXP + col] = d1[nt];
            }
        }
    }
    __syncthreads();

    // Pull this thread's hx into registers
    unsigned hxh[TT][8];
    #pragma unroll
    for (int t = 0; t < TT; t++)
        #pragma unroll
        for (int q = 0; q < 8; q++)
            hxh[t][q] = hx_s[(w * 64 + t * 32 + lane) * HXP + q];
    __syncthreads();   // hx region dead; part_s overlay may be written

    // W2 slice as half2
    __half2 w2h[8];
    {
        const float4* w2p = reinterpret_cast<const float4*>(W2 + h0);
        #pragma unroll
        for (int q = 0; q < 4; q++) {
            float4 wv = __ldg(w2p + q);
            w2h[2 * q + 0] = __floats2half2_rn(wv.x, wv.y);
            w2h[2 * q + 1] = __floats2half2_rn(wv.z, wv.w);
        }
    }

    // Pade constants (packed f32x2)
    PadeC C;
    C.c1  = pk2(1.f / 9.f,   1.f / 9.f);
    C.c2  = pk2(1.f / 945.f, 1.f / 945.f);
    C.c3  = pk2(4.f / 9.f,   4.f / 9.f);
    C.c4  = pk2(1.f / 63.f,  1.f / 63.f);
    C.one = pk2(1.f, 1.f);

    // ---- Phase B: slots 0,2,3,4,6,7 -> MUFU tanh2; slots 1,5 -> FMA Pade ----
    #pragma unroll
    for (int k = 0; k < KK; k++) {
        const uint4* hkp = reinterpret_cast<const uint4*>(&hkb_s[k * (HH / 2) + w * 8]);
        uint4 hA = hkp[0], hB = hkp[1];              // warp-uniform LDS.128
        #pragma unroll
        for (int t = 0; t < TT; t++) {
            __half2 a0, a1, a2, a3;
            a0 = __hmul2(tanh2(__hadd2(asH2(hxh[t][0]), asH2(hA.x))), w2h[0]);
            a1 = __hmul2(tanh_pade(__hadd2(asH2(hxh[t][1]), asH2(hA.y)), C), w2h[1]);
            a2 = __hmul2(tanh2(__hadd2(asH2(hxh[t][2]), asH2(hA.z))), w2h[2]);
            a3 = __hmul2(tanh2(__hadd2(asH2(hxh[t][3]), asH2(hA.w))), w2h[3]);
            a0 = __hfma2(tanh2(__hadd2(asH2(hxh[t][4]), asH2(hB.x))), w2h[4], a0);
            a1 = __hfma2(tanh_pade(__hadd2(asH2(hxh[t][5]), asH2(hB.y)), C), w2h[5], a1);
            a2 = __hfma2(tanh2(__hadd2(asH2(hxh[t][6]), asH2(hB.z))), w2h[6], a2);
            a3 = __hfma2(tanh2(__hadd2(asH2(hxh[t][7]), asH2(hB.w))), w2h[7], a3);
            __half2 a = __hadd2(__hadd2(a0, a1), __hadd2(a2, a3));
            part_s[(w * 64 + t * 32 + lane) * PRT + k] = h2bits(a);
        }
    }
    __syncthreads();

    // ---- Reduce (f32) + softmax ----
    const int tok = tid >> 2;
    const int kq  = tid & 3;
    float g[4];
    #pragma unroll
    for (int j = 0; j < 4; j++) {
        int k = 4 * kq + j;
        float s = 0.f;
        #pragma unroll
        for (int ww = 0; ww < NW; ww++) {
            float2 f = __half22float2(asH2(part_s[(ww * 64 + tok) * PRT + k]));
            s += f.x + f.y;
        }
        g[j] = s;
    }

    float m = fmaxf(fmaxf(g[0], g[1]), fmaxf(g[2], g[3]));
    m = fmaxf(m, __shfl_xor_sync(0xffffffffu, m, 1));
    m = fmaxf(m, __shfl_xor_sync(0xffffffffu, m, 2));

    float e0 = __expf(g[0] - m), e1 = __expf(g[1] - m);
    float e2 = __expf(g[2] - m), e3 = __expf(g[3] - m);
    float s = (e0 + e1) + (e2 + e3);
    s += __shfl_xor_sync(0xffffffffu, s, 1);
    s += __shfl_xor_sync(0xffffffffu, s, 2);
    float inv = __fdividef(1.f, s);

    float4 o;
    o.x = e0 * inv; o.y = e1 * inv; o.z = e2 * inv; o.w = e3 * inv;
    reinterpret_cast<float4*>(out + ((size_t)sb * NTOK + tokb + tok) * KK)[kq] = o;
}

extern "C" void kernel_launch(void* const* d_in, const int* in_sizes, int n_in,
                              void* d_out, int out_size) {
    const float* x   = (const float*)d_in[0];
    const float* mu  = (const float*)d_in[1];
    const float* tau = (const float*)d_in[2];
    const float* W1  = (const float*)d_in[3];
    const float* b1  = (const float*)d_in[4];
    const float* W2  = (const float*)d_in[5];
    // d_in[6] = b2: cancels in softmax, unused.
    float* out = (float*)d_out;

    prep_kernel<<<dim3(KK / 4, SB), TPB>>>(mu, tau, W1, b1);
    main_kernel<<<dim3(NTOK / TOKPB, SB), TPB>>>(x, W1, W2, out);
}